// round 1
// baseline (speedup 1.0000x reference)
#include <cuda_runtime.h>
#include <math.h>

#define NN 16384
#define C 64
#define KNN 40
#define TILE 2048
#define PART 1024

// ---------------- scratch (device globals; no allocation allowed) ----------
__device__ float  g_h[NN * C];       // propagated features
__device__ float4 g_s4[NN];          // learned coords (x,y,z, |s|^2)
__device__ int    g_idx[NN * KNN];   // kNN indices
__device__ float  g_ew[NN * KNN];    // edge weights
__device__ float  g_t[NN * C];       // pre-BN2 tensor (xgn + x)
__device__ float  g_v[NN * C];       // pre-BN3 tensor (y + z)
__device__ float  g_part[2][2][PART * C]; // [stage][sum|sumsq][block*C+c]
__device__ float  g_bn[4 * C];       // mu2, rstd2, mu3, rstd3

// ---------------- K1: h = x@w_h + b_h ; s = x@w_s ; pack s4 ----------------
__global__ void k1_gemm_hs(const float* __restrict__ x,
                           const float* __restrict__ w_h,
                           const float* __restrict__ b_h,
                           const float* __restrict__ w_s) {
    const int ROWS = 8;
    __shared__ float sx[ROWS][C];
    __shared__ float ss[ROWS][3];
    int base = blockIdx.x * ROWS;
    int c = threadIdx.x; // 64 threads

    #pragma unroll
    for (int r = 0; r < ROWS; r++) sx[r][c] = x[(base + r) * C + c];
    __syncthreads();

    float bias = b_h[c];
    float acc[ROWS];
    #pragma unroll
    for (int r = 0; r < ROWS; r++) acc[r] = bias;
    for (int rr = 0; rr < C; rr++) {
        float wv = w_h[rr * C + c];
        #pragma unroll
        for (int r = 0; r < ROWS; r++) acc[r] = fmaf(sx[r][rr], wv, acc[r]);
    }
    #pragma unroll
    for (int r = 0; r < ROWS; r++) g_h[(base + r) * C + c] = acc[r];

    if (c < ROWS * 3) {   // 24 threads compute s
        int r = c / 3, d = c % 3;
        float a = 0.f;
        for (int rr = 0; rr < C; rr++) a = fmaf(sx[r][rr], w_s[rr * 3 + d], a);
        ss[r][d] = a;
    }
    __syncthreads();
    if (c < ROWS) {
        float a = ss[c][0], b = ss[c][1], d = ss[c][2];
        g_s4[base + c] = make_float4(a, b, d, a * a + b * b + d * d);
    }
}

// ---------------- K2: brute-force kNN + edge weights -----------------------
__global__ void __launch_bounds__(128) k2_knn() {
    __shared__ float4 tile[TILE];
    int gid = blockIdx.x * 128 + threadIdx.x;
    float4 q = g_s4[gid];

    float bd[KNN];
    int   bi[KNN];
    #pragma unroll
    for (int j = 0; j < KNN; j++) { bd[j] = 3.4e38f; bi[j] = 0; }

    for (int t = 0; t < NN; t += TILE) {
        for (int j = threadIdx.x; j < TILE; j += 128) tile[j] = g_s4[t + j];
        __syncthreads();
        #pragma unroll 4
        for (int j = 0; j < TILE; j++) {
            float4 cp = tile[j];
            float dot = fmaf(q.x, cp.x, fmaf(q.y, cp.y, q.z * cp.z));
            float d2  = fmaf(-2.0f, dot, q.w + cp.w);   // reference selection form
            if (d2 < bd[KNN - 1]) {
                float vd = d2; int vi = t + j;
                #pragma unroll
                for (int p = 0; p < KNN; p++) {
                    if (vd < bd[p]) {
                        float td = bd[p]; bd[p] = vd; vd = td;
                        int   ti = bi[p]; bi[p] = vi; vi = ti;
                    }
                }
            }
        }
        __syncthreads();
    }

    #pragma unroll
    for (int k = 0; k < KNN; k++) {
        int j = bi[k];
        float4 cp = g_s4[j];
        float dx = q.x - cp.x, dy = q.y - cp.y, dz = q.z - cp.z;
        float d2e = dx * dx + dy * dy + dz * dz;     // reference edge-weight form
        g_idx[gid * KNN + k] = j;
        g_ew[gid * KNN + k]  = expf(-(d2e + 1e-6f));
    }
}

// ---------------- K3: aggregate + lin + residual; BN2 partials -------------
__global__ void k3_agg(const float* __restrict__ x,
                       const float* __restrict__ w_lin,
                       const float* __restrict__ b_lin) {
    __shared__ float shs[3 * C];
    int c = threadIdx.x; // 64 threads
    float psum = 0.f, psq = 0.f;
    for (int i = blockIdx.x; i < NN; i += PART) {
        float m = 0.f, mx = -3.4e38f;
        const int*   ip = &g_idx[i * KNN];
        const float* wp = &g_ew[i * KNN];
        #pragma unroll 8
        for (int k = 0; k < KNN; k++) {
            int j = ip[k];
            float w = wp[k];
            float msgv = w * g_h[j * C + c];
            m += msgv;
            mx = fmaxf(mx, msgv);
        }
        float xv = x[i * C + c];
        shs[c] = m * (1.0f / KNN);
        shs[C + c] = mx;
        shs[2 * C + c] = xv;
        __syncthreads();
        float acc = b_lin[c];
        #pragma unroll 8
        for (int r = 0; r < 3 * C; r++) acc = fmaf(shs[r], w_lin[r * C + c], acc);
        float tv = acc + xv;          // xgn + x (pre-BN2)
        g_t[i * C + c] = tv;
        psum += tv; psq += tv * tv;
        __syncthreads();
    }
    g_part[0][0][blockIdx.x * C + c] = psum;
    g_part[0][1][blockIdx.x * C + c] = psq;
}

// ---------------- finalize BN stats (deterministic) ------------------------
__global__ void kfin_stats(int stage) {
    int c = threadIdx.x; // 64 threads, 1 block
    float s = 0.f, sq = 0.f;
    for (int p = 0; p < PART; p++) {
        s  += g_part[stage][0][p * C + c];
        sq += g_part[stage][1][p * C + c];
    }
    float mu  = s * (1.0f / NN);
    float var = sq * (1.0f / NN) - mu * mu;   // biased variance
    g_bn[stage * 2 * C + c]     = mu;
    g_bn[stage * 2 * C + C + c] = rsqrtf(var + 1e-5f);
}

// ---------------- K4: BN2 + MLP + residual; BN3 partials -------------------
__global__ void k4_mlp(const float* __restrict__ w_p1, const float* __restrict__ b_p1,
                       const float* __restrict__ w_p2, const float* __restrict__ b_p2,
                       const float* __restrict__ gamma2, const float* __restrict__ beta2) {
    __shared__ float sy[C], su[C];
    int c = threadIdx.x; // 64 threads
    float mu = g_bn[c], rs = g_bn[C + c];
    float g2 = gamma2[c], be2 = beta2[c];
    float bp1 = b_p1[c], bp2 = b_p2[c];
    float psum = 0.f, psq = 0.f;
    for (int i = blockIdx.x; i < NN; i += PART) {
        float tv = g_t[i * C + c];
        float y  = fmaf((tv - mu) * rs, g2, be2);
        sy[c] = y;
        __syncthreads();
        float u = bp1;
        #pragma unroll 8
        for (int r = 0; r < C; r++) u = fmaf(sy[r], w_p1[r * C + c], u);
        u = (u > 0.f) ? u : expm1f(u);   // ELU
        su[c] = u;
        __syncthreads();
        float z = bp2;
        #pragma unroll 8
        for (int r = 0; r < C; r++) z = fmaf(su[r], w_p2[r * C + c], z);
        float v = y + z;                 // pre-BN3
        g_v[i * C + c] = v;
        psum += v; psq += v * v;
        __syncthreads();
    }
    g_part[1][0][blockIdx.x * C + c] = psum;
    g_part[1][1][blockIdx.x * C + c] = psq;
}

// ---------------- K5: final BN3 --------------------------------------------
__global__ void k5_bn3(float* __restrict__ out,
                       const float* __restrict__ gamma3,
                       const float* __restrict__ beta3) {
    int i = blockIdx.x * 256 + threadIdx.x;
    int c = i & (C - 1);
    float mu = g_bn[2 * C + c], rs = g_bn[3 * C + c];
    out[i] = fmaf((g_v[i] - mu) * rs, gamma3[c], beta3[c]);
}

// ---------------- launch ----------------------------------------------------
extern "C" void kernel_launch(void* const* d_in, const int* in_sizes, int n_in,
                              void* d_out, int out_size) {
    const float* x      = (const float*)d_in[0];
    const float* w_s    = (const float*)d_in[1];
    const float* w_h    = (const float*)d_in[2];
    const float* b_h    = (const float*)d_in[3];
    const float* w_lin  = (const float*)d_in[4];
    const float* b_lin  = (const float*)d_in[5];
    const float* w_p1   = (const float*)d_in[6];
    const float* b_p1   = (const float*)d_in[7];
    const float* w_p2   = (const float*)d_in[8];
    const float* b_p2   = (const float*)d_in[9];
    const float* gamma2 = (const float*)d_in[10];
    const float* beta2  = (const float*)d_in[11];
    const float* gamma3 = (const float*)d_in[12];
    const float* beta3  = (const float*)d_in[13];
    float* out = (float*)d_out;

    k1_gemm_hs<<<NN / 8, C>>>(x, w_h, b_h, w_s);
    k2_knn<<<NN / 128, 128>>>();
    k3_agg<<<PART, C>>>(x, w_lin, b_lin);
    kfin_stats<<<1, C>>>(0);
    k4_mlp<<<PART, C>>>(w_p1, b_p1, w_p2, b_p2, gamma2, beta2);
    kfin_stats<<<1, C>>>(1);
    k5_bn3<<<(NN * C) / 256, 256>>>(out, gamma3, beta3);
}

// round 2
// speedup vs baseline: 2.3607x; 2.3607x over previous
#include <cuda_runtime.h>
#include <math.h>

#define NN 16384
#define C 64
#define KNN 40
#define TILE 2048
#define PART 1024
#define QPW 8          // queries per warp in kNN
#define SLOTS 64       // top-64 maintained per query (2 per lane)

// ---------------- scratch (device globals; no allocation allowed) ----------
__device__ float  g_h[NN * C];       // propagated features
__device__ float4 g_s4[NN];          // learned coords (x,y,z, |s|^2)
__device__ int    g_idx[NN * KNN];   // kNN indices (arbitrary order within row)
__device__ float  g_ew[NN * KNN];    // edge weights
__device__ float  g_t[NN * C];       // pre-BN2 tensor (xgn + x)
__device__ float  g_v[NN * C];       // pre-BN3 tensor (y + z)
__device__ float  g_part[2][2][PART * C];
__device__ float  g_bn[4 * C];       // mu2, rstd2, mu3, rstd3
__device__ float  g_dummy[64];

// ---------------- tiny no-op kernels (shift ncu -s 5 onto k2_knn) ----------
__global__ void k_nop(int i) { if (threadIdx.x == 0) g_dummy[i] = 0.f; }

// ---------------- K1: h = x@w_h + b_h ; s = x@w_s ; pack s4 ----------------
__global__ void k1_gemm_hs(const float* __restrict__ x,
                           const float* __restrict__ w_h,
                           const float* __restrict__ b_h,
                           const float* __restrict__ w_s) {
    const int ROWS = 8;
    __shared__ float sx[ROWS][C];
    __shared__ float ss[ROWS][3];
    int base = blockIdx.x * ROWS;
    int c = threadIdx.x; // 64 threads

    #pragma unroll
    for (int r = 0; r < ROWS; r++) sx[r][c] = x[(base + r) * C + c];
    __syncthreads();

    float bias = b_h[c];
    float acc[ROWS];
    #pragma unroll
    for (int r = 0; r < ROWS; r++) acc[r] = bias;
    for (int rr = 0; rr < C; rr++) {
        float wv = w_h[rr * C + c];
        #pragma unroll
        for (int r = 0; r < ROWS; r++) acc[r] = fmaf(sx[r][rr], wv, acc[r]);
    }
    #pragma unroll
    for (int r = 0; r < ROWS; r++) g_h[(base + r) * C + c] = acc[r];

    if (c < ROWS * 3) {
        int r = c / 3, d = c % 3;
        float a = 0.f;
        for (int rr = 0; rr < C; rr++) a = fmaf(sx[r][rr], w_s[rr * 3 + d], a);
        ss[r][d] = a;
    }
    __syncthreads();
    if (c < ROWS) {
        float a = ss[c][0], b = ss[c][1], d = ss[c][2];
        g_s4[base + c] = make_float4(a, b, d, a * a + b * b + d * d);
    }
}

// ---------------- K2: warp-cooperative kNN (top-64 -> top-40) --------------
__device__ __forceinline__ float qdist(float qx, float qy, float qz, float qw,
                                       float4 cp) {
    float dot = fmaf(qx, cp.x, fmaf(qy, cp.y, qz * cp.z));
    return fmaf(-2.0f, dot, qw + cp.w);   // reference selection form
}

__global__ void __launch_bounds__(128, 4) k2_knn() {
    __shared__ float4 tile[TILE];
    const unsigned FULL = 0xffffffffu;
    int lane = threadIdx.x & 31;
    int wrp  = threadIdx.x >> 5;
    int qbase = blockIdx.x * (4 * QPW) + wrp * QPW;

    float qx[QPW], qy[QPW], qz[QPW], qw[QPW];
    float d0[QPW], d1[QPW], cmax[QPW];
    int   i0[QPW], i1[QPW];

    #pragma unroll
    for (int q = 0; q < QPW; q++) {
        float4 qq = g_s4[qbase + q];   // uniform broadcast load
        qx[q] = qq.x; qy[q] = qq.y; qz[q] = qq.z; qw[q] = qq.w;
    }

    // load tile 0
    for (int j = threadIdx.x; j < TILE; j += 128) tile[j] = g_s4[j];
    __syncthreads();

    // fill phase: candidates 0..63 go straight into the 2 slots
    {
        float4 c0 = tile[lane];
        float4 c1 = tile[32 + lane];
        #pragma unroll
        for (int q = 0; q < QPW; q++) {
            d0[q] = qdist(qx[q], qy[q], qz[q], qw[q], c0); i0[q] = lane;
            d1[q] = qdist(qx[q], qy[q], qz[q], qw[q], c1); i1[q] = 32 + lane;
            float lm = fmaxf(d0[q], d1[q]);
            #pragma unroll
            for (int o = 16; o; o >>= 1) lm = fmaxf(lm, __shfl_xor_sync(FULL, lm, o));
            cmax[q] = lm;
        }
    }

    for (int t = 0; t < NN; t += TILE) {
        if (t) {
            __syncthreads();
            for (int j = threadIdx.x; j < TILE; j += 128) tile[j] = g_s4[t + j];
            __syncthreads();
        }
        int jb0 = (t == 0) ? 2 : 0;
        #pragma unroll 1
        for (int jb = jb0; jb < TILE / 32; jb++) {
            float4 cp = tile[jb * 32 + lane];
            int cbase = t + jb * 32;
            #pragma unroll
            for (int q = 0; q < QPW; q++) {
                float d2 = qdist(qx[q], qy[q], qz[q], qw[q], cp);
                unsigned m = __ballot_sync(FULL, d2 < cmax[q]);
                while (m) {
                    int src = __ffs(m) - 1; m &= m - 1;
                    float dn = __shfl_sync(FULL, d2, src);
                    if (dn < cmax[q]) {
                        int ji = cbase + src;
                        bool m0 = (d0[q] == cmax[q]);
                        bool m1 = (!m0) && (d1[q] == cmax[q]);
                        unsigned bb = __ballot_sync(FULL, m0 || m1);
                        int owner = __ffs(bb) - 1;
                        if (lane == owner) {
                            if (m0) { d0[q] = dn; i0[q] = ji; }
                            else    { d1[q] = dn; i1[q] = ji; }
                        }
                        float lm = fmaxf(d0[q], d1[q]);
                        #pragma unroll
                        for (int o = 16; o; o >>= 1)
                            lm = fmaxf(lm, __shfl_xor_sync(FULL, lm, o));
                        cmax[q] = lm;
                    }
                }
            }
        }
    }

    // extraction: discard the (SLOTS-KNN)=24 largest, write the 40 survivors
    unsigned ltmask = (lane == 0) ? 0u : (0xffffffffu >> (32 - lane));
    #pragma unroll 1
    for (int q = 0; q < QPW; q++) {
        float a0 = d0[q], a1 = d1[q];
        int   j0 = i0[q], j1 = i1[q];
        #pragma unroll 1
        for (int r = 0; r < SLOTS - KNN; r++) {
            float l0 = (j0 >= 0) ? a0 : -3.4e38f;
            float l1 = (j1 >= 0) ? a1 : -3.4e38f;
            float wm = fmaxf(l0, l1);
            #pragma unroll
            for (int o = 16; o; o >>= 1) wm = fmaxf(wm, __shfl_xor_sync(FULL, wm, o));
            bool m0 = (j0 >= 0) && (l0 == wm);
            bool m1 = (!m0) && (j1 >= 0) && (l1 == wm);
            unsigned bb = __ballot_sync(FULL, m0 || m1);
            int owner = __ffs(bb) - 1;
            if (lane == owner) { if (m0) j0 = -1; else j1 = -1; }
        }
        unsigned b0 = __ballot_sync(FULL, j0 >= 0);
        unsigned b1 = __ballot_sync(FULL, j1 >= 0);
        int c0 = __popc(b0);
        int p0 = __popc(b0 & ltmask);
        int p1 = c0 + __popc(b1 & ltmask);
        int qg = qbase + q;
        if (j0 >= 0) {
            float4 cp = g_s4[j0];
            float dx = qx[q] - cp.x, dy = qy[q] - cp.y, dz = qz[q] - cp.z;
            g_idx[qg * KNN + p0] = j0;
            g_ew[qg * KNN + p0]  = expf(-(dx * dx + dy * dy + dz * dz + 1e-6f));
        }
        if (j1 >= 0) {
            float4 cp = g_s4[j1];
            float dx = qx[q] - cp.x, dy = qy[q] - cp.y, dz = qz[q] - cp.z;
            g_idx[qg * KNN + p1] = j1;
            g_ew[qg * KNN + p1]  = expf(-(dx * dx + dy * dy + dz * dz + 1e-6f));
        }
    }
}

// ---------------- K3: aggregate + lin + residual; BN2 partials -------------
__global__ void k3_agg(const float* __restrict__ x,
                       const float* __restrict__ w_lin,
                       const float* __restrict__ b_lin) {
    __shared__ float shs[3 * C];
    int c = threadIdx.x; // 64 threads
    float psum = 0.f, psq = 0.f;
    for (int i = blockIdx.x; i < NN; i += PART) {
        float m = 0.f, mx = -3.4e38f;
        const int*   ip = &g_idx[i * KNN];
        const float* wp = &g_ew[i * KNN];
        #pragma unroll 8
        for (int k = 0; k < KNN; k++) {
            int j = ip[k];
            float w = wp[k];
            float msgv = w * g_h[j * C + c];
            m += msgv;
            mx = fmaxf(mx, msgv);
        }
        float xv = x[i * C + c];
        shs[c] = m * (1.0f / KNN);
        shs[C + c] = mx;
        shs[2 * C + c] = xv;
        __syncthreads();
        float acc = b_lin[c];
        #pragma unroll 8
        for (int r = 0; r < 3 * C; r++) acc = fmaf(shs[r], w_lin[r * C + c], acc);
        float tv = acc + xv;
        g_t[i * C + c] = tv;
        psum += tv; psq += tv * tv;
        __syncthreads();
    }
    g_part[0][0][blockIdx.x * C + c] = psum;
    g_part[0][1][blockIdx.x * C + c] = psq;
}

// ---------------- finalize BN stats (deterministic, parallel) --------------
__global__ void kfin_stats(int stage) {
    __shared__ float red[2][1024];
    int t = threadIdx.x;             // 1024 threads
    int c = t & (C - 1);
    int g = t >> 6;                  // 16 groups
    float s = 0.f, sq = 0.f;
    for (int p = g; p < PART; p += 16) {
        s  += g_part[stage][0][p * C + c];
        sq += g_part[stage][1][p * C + c];
    }
    red[0][t] = s; red[1][t] = sq;
    __syncthreads();
    #pragma unroll
    for (int off = 512; off >= 64; off >>= 1) {
        if (t < off) { red[0][t] += red[0][t + off]; red[1][t] += red[1][t + off]; }
        __syncthreads();
    }
    if (t < C) {
        float mu  = red[0][t] * (1.0f / NN);
        float var = red[1][t] * (1.0f / NN) - mu * mu;
        g_bn[stage * 2 * C + t]     = mu;
        g_bn[stage * 2 * C + C + t] = rsqrtf(var + 1e-5f);
    }
}

// ---------------- K4: BN2 + MLP + residual; BN3 partials -------------------
__global__ void k4_mlp(const float* __restrict__ w_p1, const float* __restrict__ b_p1,
                       const float* __restrict__ w_p2, const float* __restrict__ b_p2,
                       const float* __restrict__ gamma2, const float* __restrict__ beta2) {
    __shared__ float sy[C], su[C];
    int c = threadIdx.x; // 64 threads
    float mu = g_bn[c], rs = g_bn[C + c];
    float g2 = gamma2[c], be2 = beta2[c];
    float bp1 = b_p1[c], bp2 = b_p2[c];
    float psum = 0.f, psq = 0.f;
    for (int i = blockIdx.x; i < NN; i += PART) {
        float tv = g_t[i * C + c];
        float y  = fmaf((tv - mu) * rs, g2, be2);
        sy[c] = y;
        __syncthreads();
        float u = bp1;
        #pragma unroll 8
        for (int r = 0; r < C; r++) u = fmaf(sy[r], w_p1[r * C + c], u);
        u = (u > 0.f) ? u : expm1f(u);   // ELU
        su[c] = u;
        __syncthreads();
        float z = bp2;
        #pragma unroll 8
        for (int r = 0; r < C; r++) z = fmaf(su[r], w_p2[r * C + c], z);
        float v = y + z;
        g_v[i * C + c] = v;
        psum += v; psq += v * v;
        __syncthreads();
    }
    g_part[1][0][blockIdx.x * C + c] = psum;
    g_part[1][1][blockIdx.x * C + c] = psq;
}

// ---------------- K5: final BN3 --------------------------------------------
__global__ void k5_bn3(float* __restrict__ out,
                       const float* __restrict__ gamma3,
                       const float* __restrict__ beta3) {
    int i = blockIdx.x * 256 + threadIdx.x;
    int c = i & (C - 1);
    float mu = g_bn[2 * C + c], rs = g_bn[3 * C + c];
    out[i] = fmaf((g_v[i] - mu) * rs, gamma3[c], beta3[c]);
}

// ---------------- launch ----------------------------------------------------
extern "C" void kernel_launch(void* const* d_in, const int* in_sizes, int n_in,
                              void* d_out, int out_size) {
    const float* x      = (const float*)d_in[0];
    const float* w_s    = (const float*)d_in[1];
    const float* w_h    = (const float*)d_in[2];
    const float* b_h    = (const float*)d_in[3];
    const float* w_lin  = (const float*)d_in[4];
    const float* b_lin  = (const float*)d_in[5];
    const float* w_p1   = (const float*)d_in[6];
    const float* b_p1   = (const float*)d_in[7];
    const float* w_p2   = (const float*)d_in[8];
    const float* b_p2   = (const float*)d_in[9];
    const float* gamma2 = (const float*)d_in[10];
    const float* beta2  = (const float*)d_in[11];
    const float* gamma3 = (const float*)d_in[12];
    const float* beta3  = (const float*)d_in[13];
    float* out = (float*)d_out;

    // 4 cheap launches so ncu (-s 5 -c 1) profiles k2_knn next round
    k_nop<<<1, 32>>>(0);
    k_nop<<<1, 32>>>(1);
    k_nop<<<1, 32>>>(2);
    k_nop<<<1, 32>>>(3);

    k1_gemm_hs<<<NN / 8, C>>>(x, w_h, b_h, w_s);
    k2_knn<<<NN / 32, 128>>>();
    k3_agg<<<PART, C>>>(x, w_lin, b_lin);
    kfin_stats<<<1, 1024>>>(0);
    k4_mlp<<<PART, C>>>(w_p1, b_p1, w_p2, b_p2, gamma2, beta2);
    kfin_stats<<<1, 1024>>>(1);
    k5_bn3<<<(NN * C) / 256, 256>>>(out, gamma3, beta3);
}

// round 3
// speedup vs baseline: 3.6151x; 1.5313x over previous
#include <cuda_runtime.h>
#include <math.h>

#define NN 16384
#define C 64
#define KNN 40
#define TILE4 1024     // float4 candidates per smem tile
#define CAP 96         // collection capacity per query
#define PART 2048      // partial-reduction blocks for BN stats

// ---------------- scratch (device globals; no allocation allowed) ----------
__device__ float  g_h[NN * C];       // propagated features
__device__ float4 g_s4[NN];          // learned coords (x,y,z,|s|^2)
__device__ int    g_idx[NN * KNN];   // kNN indices
__device__ float  g_ew[NN * KNN];    // edge weights
__device__ float  g_t[NN * C];       // pre-BN2 tensor
__device__ float  g_v[NN * C];       // pre-BN3 tensor
__device__ float  g_part[2][2][PART * C];
__device__ float  g_bn[4 * C];       // mu2, rstd2, mu3, rstd3

// ---------------- K1: h = x@w_h + b_h ; s = x@w_s ; pack s4 ----------------
__global__ void k1_gemm_hs(const float* __restrict__ x,
                           const float* __restrict__ w_h,
                           const float* __restrict__ b_h,
                           const float* __restrict__ w_s) {
    const int ROWS = 8;
    __shared__ float sx[ROWS][C];
    __shared__ float ss[ROWS][3];
    int base = blockIdx.x * ROWS;
    int c = threadIdx.x; // 64 threads

    #pragma unroll
    for (int r = 0; r < ROWS; r++) sx[r][c] = x[(base + r) * C + c];
    __syncthreads();

    float bias = b_h[c];
    float acc[ROWS];
    #pragma unroll
    for (int r = 0; r < ROWS; r++) acc[r] = bias;
    for (int rr = 0; rr < C; rr++) {
        float wv = w_h[rr * C + c];
        #pragma unroll
        for (int r = 0; r < ROWS; r++) acc[r] = fmaf(sx[r][rr], wv, acc[r]);
    }
    #pragma unroll
    for (int r = 0; r < ROWS; r++) g_h[(base + r) * C + c] = acc[r];

    if (c < ROWS * 3) {
        int r = c / 3, d = c % 3;
        float a = 0.f;
        for (int rr = 0; rr < C; rr++) a = fmaf(sx[r][rr], w_s[rr * 3 + d], a);
        ss[r][d] = a;
    }
    __syncthreads();
    if (c < ROWS) {
        float a = ss[c][0], b = ss[c][1], d = ss[c][2];
        g_s4[base + c] = make_float4(a, b, d, a * a + b * b + d * d);
    }
}

// ---------------- K2: exact two-pass threshold kNN -------------------------
__device__ __forceinline__ float qdist(float qx, float qy, float qz, float qw,
                                       float4 cp) {
    float dot = fmaf(qx, cp.x, fmaf(qy, cp.y, qz * cp.z));
    return fmaf(-2.0f, dot, qw + cp.w);   // reference selection form
}

__global__ void __launch_bounds__(128, 4) k2_knn() {
    __shared__ float4 tile[TILE4];
    __shared__ float  skey[32][CAP];
    __shared__ int    sidx[32][CAP];
    const unsigned FULL = 0xffffffffu;
    const float INF = 3.4e38f;
    int lane = threadIdx.x & 31;
    int wrp  = threadIdx.x >> 5;
    int qbase = blockIdx.x * 32 + wrp * 8;

    float qx[8], qy[8], qz[8], qw[8];
    #pragma unroll
    for (int q = 0; q < 8; q++) {
        float4 qq = g_s4[qbase + q];
        qx[q] = qq.x; qy[q] = qq.y; qz[q] = qq.z; qw[q] = qq.w;
    }

    // ---- sweep A: lane-private sorted top-4 distances (values only) ----
    float t0[8], t1[8], t2[8], t3[8];
    #pragma unroll
    for (int q = 0; q < 8; q++) { t0[q] = INF; t1[q] = INF; t2[q] = INF; t3[q] = INF; }

    for (int t = 0; t < NN; t += TILE4) {
        __syncthreads();
        for (int j = threadIdx.x; j < TILE4; j += 128) tile[j] = g_s4[t + j];
        __syncthreads();
        #pragma unroll 2
        for (int jb = 0; jb < TILE4 / 32; jb++) {
            float4 cp = tile[jb * 32 + lane];
            #pragma unroll
            for (int q = 0; q < 8; q++) {
                float a = qdist(qx[q], qy[q], qz[q], qw[q], cp);
                if (a < t3[q]) {
                    if (a < t2[q]) {
                        t3[q] = t2[q];
                        if (a < t1[q]) {
                            t2[q] = t1[q];
                            if (a < t0[q]) { t1[q] = t0[q]; t0[q] = a; }
                            else t1[q] = a;
                        } else t2[q] = a;
                    } else t3[q] = a;
                }
            }
        }
    }

    // ---- tau[q] = 40th smallest of the kept 128 values (>= true 40th) ----
    float tau[8];
    #pragma unroll 1
    for (int q = 0; q < 8; q++) {
        float h0 = t0[q], h1 = t1[q], h2 = t2[q], h3 = t3[q];
        float m = INF;
        #pragma unroll 1
        for (int r = 0; r < KNN; r++) {
            m = h0;
            #pragma unroll
            for (int o = 16; o; o >>= 1) m = fminf(m, __shfl_xor_sync(FULL, m, o));
            unsigned bb = __ballot_sync(FULL, h0 == m);
            if (lane == __ffs(bb) - 1) { h0 = h1; h1 = h2; h2 = h3; h3 = INF; }
        }
        tau[q] = m;
    }

    // ---- sweep B: collect all candidates with d2 <= tau ----
    int cnt[8];
    #pragma unroll
    for (int q = 0; q < 8; q++) cnt[q] = 0;
    unsigned ltmask = (1u << lane) - 1u;

    for (int t = 0; t < NN; t += TILE4) {
        __syncthreads();
        for (int j = threadIdx.x; j < TILE4; j += 128) tile[j] = g_s4[t + j];
        __syncthreads();
        #pragma unroll 2
        for (int jb = 0; jb < TILE4 / 32; jb++) {
            float4 cp = tile[jb * 32 + lane];
            int ci = t + jb * 32 + lane;
            #pragma unroll
            for (int q = 0; q < 8; q++) {
                float d2 = qdist(qx[q], qy[q], qz[q], qw[q], cp);
                bool hit = (d2 <= tau[q]);
                unsigned mm = __ballot_sync(FULL, hit);
                if (mm) {
                    int pos = cnt[q] + __popc(mm & ltmask);
                    if (hit && pos < CAP) {
                        skey[wrp * 8 + q][pos] = d2;
                        sidx[wrp * 8 + q][pos] = ci;
                    }
                    cnt[q] += __popc(mm);
                }
            }
        }
    }

    // ---- final: exact rank-(d2,idx) selection of top-40 from collection ----
    #pragma unroll 1
    for (int q = 0; q < 8; q++) {
        int n = cnt[q] < CAP ? cnt[q] : CAP;
        int qs = wrp * 8 + q;
        int qg = qbase + q;
        #pragma unroll 1
        for (int base = 0; base < CAP; base += 32) {
            int p = base + lane;
            if (p < n) {
                float d = skey[qs][p];
                int  id = sidx[qs][p];
                int rank = 0;
                for (int e = 0; e < n; e++) {
                    float de = skey[qs][e];
                    int   ie = sidx[qs][e];
                    rank += (de < d) || (de == d && ie < id);
                }
                if (rank < KNN) {
                    float4 cp = g_s4[id];
                    float dx = qx[q] - cp.x, dy = qy[q] - cp.y, dz = qz[q] - cp.z;
                    g_idx[qg * KNN + rank] = id;
                    g_ew[qg * KNN + rank]  = expf(-(dx * dx + dy * dy + dz * dz + 1e-6f));
                }
            }
        }
    }
}

// ---------------- K3: aggregate + lin + residual; BN2 partials -------------
__global__ void k3_agg(const float* __restrict__ x,
                       const float* __restrict__ w_lin,
                       const float* __restrict__ b_lin) {
    __shared__ float shs[3 * C];
    int c = threadIdx.x; // 64 threads
    float psum = 0.f, psq = 0.f;
    for (int i = blockIdx.x; i < NN; i += PART) {
        float m = 0.f, mx = -3.4e38f;
        const int*   ip = &g_idx[i * KNN];
        const float* wp = &g_ew[i * KNN];
        #pragma unroll 8
        for (int k = 0; k < KNN; k++) {
            int j = ip[k];
            float w = wp[k];
            float msgv = w * g_h[j * C + c];
            m += msgv;
            mx = fmaxf(mx, msgv);
        }
        float xv = x[i * C + c];
        shs[c] = m * (1.0f / KNN);
        shs[C + c] = mx;
        shs[2 * C + c] = xv;
        __syncthreads();
        float a0 = 0.f, a1 = 0.f, a2 = 0.f, a3 = 0.f;
        #pragma unroll 4
        for (int r = 0; r < 3 * C; r += 4) {
            a0 = fmaf(shs[r + 0], w_lin[(r + 0) * C + c], a0);
            a1 = fmaf(shs[r + 1], w_lin[(r + 1) * C + c], a1);
            a2 = fmaf(shs[r + 2], w_lin[(r + 2) * C + c], a2);
            a3 = fmaf(shs[r + 3], w_lin[(r + 3) * C + c], a3);
        }
        float tv = ((a0 + a1) + (a2 + a3)) + b_lin[c] + xv;
        g_t[i * C + c] = tv;
        psum += tv; psq += tv * tv;
        __syncthreads();
    }
    g_part[0][0][blockIdx.x * C + c] = psum;
    g_part[0][1][blockIdx.x * C + c] = psq;
}

// ---------------- finalize BN stats (deterministic, parallel) --------------
__global__ void kfin_stats(int stage) {
    __shared__ float red[2][1024];
    int t = threadIdx.x;             // 1024 threads
    int c = t & (C - 1);
    int g = t >> 6;                  // 16 groups
    float s = 0.f, sq = 0.f;
    for (int p = g; p < PART; p += 16) {
        s  += g_part[stage][0][p * C + c];
        sq += g_part[stage][1][p * C + c];
    }
    red[0][t] = s; red[1][t] = sq;
    __syncthreads();
    #pragma unroll
    for (int off = 512; off >= 64; off >>= 1) {
        if (t < off) { red[0][t] += red[0][t + off]; red[1][t] += red[1][t + off]; }
        __syncthreads();
    }
    if (t < C) {
        float mu  = red[0][t] * (1.0f / NN);
        float var = red[1][t] * (1.0f / NN) - mu * mu;
        g_bn[stage * 2 * C + t]     = mu;
        g_bn[stage * 2 * C + C + t] = rsqrtf(var + 1e-5f);
    }
}

// ---------------- K4: BN2 + MLP + residual; BN3 partials -------------------
__global__ void k4_mlp(const float* __restrict__ w_p1, const float* __restrict__ b_p1,
                       const float* __restrict__ w_p2, const float* __restrict__ b_p2,
                       const float* __restrict__ gamma2, const float* __restrict__ beta2) {
    __shared__ float sy[C], su[C];
    int c = threadIdx.x; // 64 threads
    float mu = g_bn[c], rs = g_bn[C + c];
    float g2 = gamma2[c], be2 = beta2[c];
    float bp1 = b_p1[c], bp2 = b_p2[c];
    float psum = 0.f, psq = 0.f;
    for (int i = blockIdx.x; i < NN; i += PART) {
        float tv = g_t[i * C + c];
        float y  = fmaf((tv - mu) * rs, g2, be2);
        sy[c] = y;
        __syncthreads();
        float a0 = 0.f, a1 = 0.f, a2 = 0.f, a3 = 0.f;
        #pragma unroll 4
        for (int r = 0; r < C; r += 4) {
            a0 = fmaf(sy[r + 0], w_p1[(r + 0) * C + c], a0);
            a1 = fmaf(sy[r + 1], w_p1[(r + 1) * C + c], a1);
            a2 = fmaf(sy[r + 2], w_p1[(r + 2) * C + c], a2);
            a3 = fmaf(sy[r + 3], w_p1[(r + 3) * C + c], a3);
        }
        float u = ((a0 + a1) + (a2 + a3)) + bp1;
        u = (u > 0.f) ? u : expm1f(u);   // ELU
        su[c] = u;
        __syncthreads();
        float z0 = 0.f, z1 = 0.f, z2 = 0.f, z3 = 0.f;
        #pragma unroll 4
        for (int r = 0; r < C; r += 4) {
            z0 = fmaf(su[r + 0], w_p2[(r + 0) * C + c], z0);
            z1 = fmaf(su[r + 1], w_p2[(r + 1) * C + c], z1);
            z2 = fmaf(su[r + 2], w_p2[(r + 2) * C + c], z2);
            z3 = fmaf(su[r + 3], w_p2[(r + 3) * C + c], z3);
        }
        float v = y + ((z0 + z1) + (z2 + z3)) + bp2;
        g_v[i * C + c] = v;
        psum += v; psq += v * v;
        __syncthreads();
    }
    g_part[1][0][blockIdx.x * C + c] = psum;
    g_part[1][1][blockIdx.x * C + c] = psq;
}

// ---------------- K5: final BN3 --------------------------------------------
__global__ void k5_bn3(float* __restrict__ out,
                       const float* __restrict__ gamma3,
                       const float* __restrict__ beta3) {
    int i = blockIdx.x * 256 + threadIdx.x;
    int c = i & (C - 1);
    float mu = g_bn[2 * C + c], rs = g_bn[3 * C + c];
    out[i] = fmaf((g_v[i] - mu) * rs, gamma3[c], beta3[c]);
}

// ---------------- launch ----------------------------------------------------
extern "C" void kernel_launch(void* const* d_in, const int* in_sizes, int n_in,
                              void* d_out, int out_size) {
    const float* x      = (const float*)d_in[0];
    const float* w_s    = (const float*)d_in[1];
    const float* w_h    = (const float*)d_in[2];
    const float* b_h    = (const float*)d_in[3];
    const float* w_lin  = (const float*)d_in[4];
    const float* b_lin  = (const float*)d_in[5];
    const float* w_p1   = (const float*)d_in[6];
    const float* b_p1   = (const float*)d_in[7];
    const float* w_p2   = (const float*)d_in[8];
    const float* b_p2   = (const float*)d_in[9];
    const float* gamma2 = (const float*)d_in[10];
    const float* beta2  = (const float*)d_in[11];
    const float* gamma3 = (const float*)d_in[12];
    const float* beta3  = (const float*)d_in[13];
    float* out = (float*)d_out;

    k1_gemm_hs<<<NN / 8, C>>>(x, w_h, b_h, w_s);
    k2_knn<<<NN / 32, 128>>>();
    k3_agg<<<PART, C>>>(x, w_lin, b_lin);
    kfin_stats<<<1, 1024>>>(0);
    k4_mlp<<<PART, C>>>(w_p1, b_p1, w_p2, b_p2, gamma2, beta2);
    kfin_stats<<<1, 1024>>>(1);
    k5_bn3<<<(NN * C) / 256, 256>>>(out, gamma3, beta3);
}

// round 4
// speedup vs baseline: 4.1101x; 1.1369x over previous
#include <cuda_runtime.h>
#include <math.h>

#define NN 16384
#define C 64
#define KNN 40
#define TILE4 1024     // float4 candidates per smem tile
#define CAP 96         // collection capacity per query
#define QPW 4          // queries per warp in kNN
#define PART 512       // partial-reduction blocks for BN stats

// ---------------- scratch (device globals; no allocation allowed) ----------
__device__ float  g_h[NN * C];       // propagated features
__device__ float4 g_s4[NN];          // learned coords (x,y,z,|s|^2)
__device__ int    g_idx[NN * KNN];   // kNN indices
__device__ float  g_ew[NN * KNN];    // edge weights
__device__ float  g_t[NN * C];       // pre-BN2 tensor
__device__ float  g_v[NN * C];       // pre-BN3 tensor
__device__ float  g_part[2][2][PART * C];
__device__ float  g_bn[4 * C];       // mu2, rstd2, mu3, rstd3

// ---------------- K1: h = x@w_h + b_h ; s = x@w_s ; pack s4 ----------------
__global__ void k1_gemm_hs(const float* __restrict__ x,
                           const float* __restrict__ w_h,
                           const float* __restrict__ b_h,
                           const float* __restrict__ w_s) {
    const int ROWS = 8;
    __shared__ float sx[ROWS][C];
    __shared__ float ss[ROWS][3];
    int base = blockIdx.x * ROWS;
    int c = threadIdx.x; // 64 threads

    #pragma unroll
    for (int r = 0; r < ROWS; r++) sx[r][c] = x[(base + r) * C + c];
    __syncthreads();

    float bias = b_h[c];
    float acc[ROWS];
    #pragma unroll
    for (int r = 0; r < ROWS; r++) acc[r] = bias;
    for (int rr = 0; rr < C; rr++) {
        float wv = w_h[rr * C + c];
        #pragma unroll
        for (int r = 0; r < ROWS; r++) acc[r] = fmaf(sx[r][rr], wv, acc[r]);
    }
    #pragma unroll
    for (int r = 0; r < ROWS; r++) g_h[(base + r) * C + c] = acc[r];

    if (c < ROWS * 3) {
        int r = c / 3, d = c % 3;
        float a = 0.f;
        for (int rr = 0; rr < C; rr++) a = fmaf(sx[r][rr], w_s[rr * 3 + d], a);
        ss[r][d] = a;
    }
    __syncthreads();
    if (c < ROWS) {
        float a = ss[c][0], b = ss[c][1], d = ss[c][2];
        g_s4[base + c] = make_float4(a, b, d, a * a + b * b + d * d);
    }
}

// ---------------- K2: exact two-pass threshold kNN -------------------------
__device__ __forceinline__ float qdist(float qx, float qy, float qz, float qw,
                                       float4 cp) {
    float dot = fmaf(qx, cp.x, fmaf(qy, cp.y, qz * cp.z));
    return fmaf(-2.0f, dot, qw + cp.w);   // reference selection form
}

__global__ void __launch_bounds__(256) k2_knn() {
    __shared__ float4 tile[TILE4];
    __shared__ float  skey[32][CAP];
    __shared__ int    sidx[32][CAP];
    const unsigned FULL = 0xffffffffu;
    const float INF = 3.4e38f;
    int lane = threadIdx.x & 31;
    int wrp  = threadIdx.x >> 5;       // 8 warps
    int qbase = blockIdx.x * 32 + wrp * QPW;

    float qx[QPW], qy[QPW], qz[QPW], qw[QPW];
    #pragma unroll
    for (int q = 0; q < QPW; q++) {
        float4 qq = g_s4[qbase + q];
        qx[q] = qq.x; qy[q] = qq.y; qz[q] = qq.z; qw[q] = qq.w;
    }

    // ---- sweep A: lane-private sorted top-4 distances (values only) ----
    float t0[QPW], t1[QPW], t2[QPW], t3[QPW];
    #pragma unroll
    for (int q = 0; q < QPW; q++) { t0[q] = INF; t1[q] = INF; t2[q] = INF; t3[q] = INF; }

    for (int t = 0; t < NN; t += TILE4) {
        __syncthreads();
        for (int j = threadIdx.x; j < TILE4; j += 256) tile[j] = g_s4[t + j];
        __syncthreads();
        #pragma unroll 2
        for (int jb = 0; jb < TILE4 / 32; jb++) {
            float4 cp = tile[jb * 32 + lane];
            #pragma unroll
            for (int q = 0; q < QPW; q++) {
                float a = qdist(qx[q], qy[q], qz[q], qw[q], cp);
                if (a < t3[q]) {
                    if (a < t2[q]) {
                        t3[q] = t2[q];
                        if (a < t1[q]) {
                            t2[q] = t1[q];
                            if (a < t0[q]) { t1[q] = t0[q]; t0[q] = a; }
                            else t1[q] = a;
                        } else t2[q] = a;
                    } else t3[q] = a;
                }
            }
        }
    }

    // ---- tau[q] = 40th smallest of kept 128 values (>= true 40th dist) ----
    float tau[QPW];
    #pragma unroll 1
    for (int q = 0; q < QPW; q++) {
        float h0 = t0[q], h1 = t1[q], h2 = t2[q], h3 = t3[q];
        float m = INF;
        #pragma unroll 1
        for (int r = 0; r < KNN; r++) {
            m = h0;
            #pragma unroll
            for (int o = 16; o; o >>= 1) m = fminf(m, __shfl_xor_sync(FULL, m, o));
            unsigned bb = __ballot_sync(FULL, h0 == m);
            if (lane == __ffs(bb) - 1) { h0 = h1; h1 = h2; h2 = h3; h3 = INF; }
        }
        tau[q] = m;
    }

    // ---- sweep B: collect all candidates with d2 <= tau ----
    int cnt[QPW];
    #pragma unroll
    for (int q = 0; q < QPW; q++) cnt[q] = 0;
    unsigned ltmask = (1u << lane) - 1u;

    for (int t = 0; t < NN; t += TILE4) {
        __syncthreads();
        for (int j = threadIdx.x; j < TILE4; j += 256) tile[j] = g_s4[t + j];
        __syncthreads();
        #pragma unroll 2
        for (int jb = 0; jb < TILE4 / 32; jb++) {
            float4 cp = tile[jb * 32 + lane];
            int ci = t + jb * 32 + lane;
            #pragma unroll
            for (int q = 0; q < QPW; q++) {
                float d2 = qdist(qx[q], qy[q], qz[q], qw[q], cp);
                bool hit = (d2 <= tau[q]);
                unsigned mm = __ballot_sync(FULL, hit);
                if (mm) {
                    int pos = cnt[q] + __popc(mm & ltmask);
                    if (hit && pos < CAP) {
                        skey[wrp * QPW + q][pos] = d2;
                        sidx[wrp * QPW + q][pos] = ci;
                    }
                    cnt[q] += __popc(mm);
                }
            }
        }
    }

    // ---- final: exact rank-(d2,idx) top-40 from the small collection ----
    #pragma unroll 1
    for (int q = 0; q < QPW; q++) {
        int n = cnt[q] < CAP ? cnt[q] : CAP;
        int qs = wrp * QPW + q;
        int qg = qbase + q;
        #pragma unroll 1
        for (int base = 0; base < n; base += 32) {
            int p = base + lane;
            if (p < n) {
                float d = skey[qs][p];
                int  id = sidx[qs][p];
                int rank = 0;
                for (int e = 0; e < n; e++) {
                    float de = skey[qs][e];
                    int   ie = sidx[qs][e];
                    rank += (de < d) || (de == d && ie < id);
                }
                if (rank < KNN) {
                    float4 cp = g_s4[id];
                    float dx = qx[q] - cp.x, dy = qy[q] - cp.y, dz = qz[q] - cp.z;
                    g_idx[qg * KNN + rank] = id;
                    g_ew[qg * KNN + rank]  = expf(-(dx * dx + dy * dy + dz * dz + 1e-6f));
                }
            }
        }
    }
}

// ---------------- K3: aggregate + lin + residual; BN2 partials -------------
// 256 threads: 4 groups of 64; each group batches 4 nodes; w_lin in smem.
__global__ void __launch_bounds__(256) k3_agg(const float* __restrict__ x,
                                              const float* __restrict__ w_lin,
                                              const float* __restrict__ b_lin) {
    __shared__ float  swl[3 * C * C];      // 48KB
    __shared__ float4 shs4[4][3 * C];      // 12KB: [group][row] x 4 nodes
    __shared__ float  sred[2][256];
    int tid = threadIdx.x;
    int g = tid >> 6, c = tid & 63;

    for (int i = tid; i < 3 * C * C; i += 256) swl[i] = w_lin[i];
    float blc = b_lin[c];
    float psum = 0.f, psq = 0.f;

    for (int ii = blockIdx.x * 16; ii < NN; ii += PART * 16) {
        float mv[4], mxv[4], xr[4];
        #pragma unroll
        for (int b = 0; b < 4; b++) {
            int i = ii + g * 4 + b;
            const int*   ip = &g_idx[i * KNN];
            const float* wp = &g_ew[i * KNN];
            float m = 0.f, mx = -3.4e38f;
            #pragma unroll 8
            for (int k = 0; k < KNN; k++) {
                float msg = wp[k] * g_h[ip[k] * C + c];
                m += msg;
                mx = fmaxf(mx, msg);
            }
            mv[b] = m * (1.0f / KNN); mxv[b] = mx;
            xr[b] = x[i * C + c];
        }
        #pragma unroll
        for (int b = 0; b < 4; b++) {
            ((float*)&shs4[g][c])[b]         = mv[b];
            ((float*)&shs4[g][C + c])[b]     = mxv[b];
            ((float*)&shs4[g][2 * C + c])[b] = xr[b];
        }
        __syncthreads();   // covers swl on first iter + shs4 writes
        float a0 = 0.f, a1 = 0.f, a2 = 0.f, a3 = 0.f;
        #pragma unroll 4
        for (int r = 0; r < 3 * C; r++) {
            float4 v = shs4[g][r];
            float w = swl[r * C + c];
            a0 = fmaf(v.x, w, a0); a1 = fmaf(v.y, w, a1);
            a2 = fmaf(v.z, w, a2); a3 = fmaf(v.w, w, a3);
        }
        float tv0 = a0 + blc + xr[0], tv1 = a1 + blc + xr[1];
        float tv2 = a2 + blc + xr[2], tv3 = a3 + blc + xr[3];
        int i0 = ii + g * 4;
        g_t[(i0 + 0) * C + c] = tv0; g_t[(i0 + 1) * C + c] = tv1;
        g_t[(i0 + 2) * C + c] = tv2; g_t[(i0 + 3) * C + c] = tv3;
        psum += (tv0 + tv1) + (tv2 + tv3);
        psq  += (tv0 * tv0 + tv1 * tv1) + (tv2 * tv2 + tv3 * tv3);
        __syncthreads();   // before next iter rewrites shs4
    }
    sred[0][tid] = psum; sred[1][tid] = psq;
    __syncthreads();
    if (tid < 64) {
        float s  = sred[0][tid] + sred[0][tid + 64] + sred[0][tid + 128] + sred[0][tid + 192];
        float sq = sred[1][tid] + sred[1][tid + 64] + sred[1][tid + 128] + sred[1][tid + 192];
        g_part[0][0][blockIdx.x * C + tid] = s;
        g_part[0][1][blockIdx.x * C + tid] = sq;
    }
}

// ---------------- finalize BN stats (deterministic, parallel) --------------
__global__ void kfin_stats(int stage) {
    __shared__ float red[2][1024];
    int t = threadIdx.x;             // 1024 threads
    int c = t & (C - 1);
    int g = t >> 6;                  // 16 groups
    float s = 0.f, sq = 0.f;
    for (int p = g; p < PART; p += 16) {
        s  += g_part[stage][0][p * C + c];
        sq += g_part[stage][1][p * C + c];
    }
    red[0][t] = s; red[1][t] = sq;
    __syncthreads();
    #pragma unroll
    for (int off = 512; off >= 64; off >>= 1) {
        if (t < off) { red[0][t] += red[0][t + off]; red[1][t] += red[1][t + off]; }
        __syncthreads();
    }
    if (t < C) {
        float mu  = red[0][t] * (1.0f / NN);
        float var = red[1][t] * (1.0f / NN) - mu * mu;
        g_bn[stage * 2 * C + t]     = mu;
        g_bn[stage * 2 * C + C + t] = rsqrtf(var + 1e-5f);
    }
}

// ---------------- K4: BN2 + MLP + residual; BN3 partials -------------------
__global__ void __launch_bounds__(256) k4_mlp(const float* __restrict__ w_p1,
                                              const float* __restrict__ b_p1,
                                              const float* __restrict__ w_p2,
                                              const float* __restrict__ b_p2,
                                              const float* __restrict__ gamma2,
                                              const float* __restrict__ beta2) {
    __shared__ float  w1s[C * C], w2s[C * C];   // 32KB
    __shared__ float4 sy4[4][C], su4[4][C];     // 4KB
    __shared__ float  sred[2][256];
    int tid = threadIdx.x;
    int g = tid >> 6, c = tid & 63;

    for (int i = tid; i < C * C; i += 256) { w1s[i] = w_p1[i]; w2s[i] = w_p2[i]; }
    float mu = g_bn[c], rs = g_bn[C + c];
    float g2 = gamma2[c], be2 = beta2[c];
    float bp1 = b_p1[c], bp2 = b_p2[c];
    float psum = 0.f, psq = 0.f;

    for (int ii = blockIdx.x * 16; ii < NN; ii += PART * 16) {
        int i0 = ii + g * 4;
        float y[4];
        #pragma unroll
        for (int b = 0; b < 4; b++) {
            float tv = g_t[(i0 + b) * C + c];
            y[b] = fmaf((tv - mu) * rs, g2, be2);
            ((float*)&sy4[g][c])[b] = y[b];
        }
        __syncthreads();   // covers w1s/w2s on first iter + sy4 writes
        float a0 = 0.f, a1 = 0.f, a2 = 0.f, a3 = 0.f;
        #pragma unroll 4
        for (int r = 0; r < C; r++) {
            float4 v = sy4[g][r];
            float w = w1s[r * C + c];
            a0 = fmaf(v.x, w, a0); a1 = fmaf(v.y, w, a1);
            a2 = fmaf(v.z, w, a2); a3 = fmaf(v.w, w, a3);
        }
        a0 += bp1; a1 += bp1; a2 += bp1; a3 += bp1;
        a0 = (a0 > 0.f) ? a0 : expm1f(a0);
        a1 = (a1 > 0.f) ? a1 : expm1f(a1);
        a2 = (a2 > 0.f) ? a2 : expm1f(a2);
        a3 = (a3 > 0.f) ? a3 : expm1f(a3);
        ((float*)&su4[g][c])[0] = a0; ((float*)&su4[g][c])[1] = a1;
        ((float*)&su4[g][c])[2] = a2; ((float*)&su4[g][c])[3] = a3;
        __syncthreads();
        float z0 = 0.f, z1 = 0.f, z2 = 0.f, z3 = 0.f;
        #pragma unroll 4
        for (int r = 0; r < C; r++) {
            float4 v = su4[g][r];
            float w = w2s[r * C + c];
            z0 = fmaf(v.x, w, z0); z1 = fmaf(v.y, w, z1);
            z2 = fmaf(v.z, w, z2); z3 = fmaf(v.w, w, z3);
        }
        float v0 = y[0] + z0 + bp2, v1 = y[1] + z1 + bp2;
        float v2 = y[2] + z2 + bp2, v3 = y[3] + z3 + bp2;
        g_v[(i0 + 0) * C + c] = v0; g_v[(i0 + 1) * C + c] = v1;
        g_v[(i0 + 2) * C + c] = v2; g_v[(i0 + 3) * C + c] = v3;
        psum += (v0 + v1) + (v2 + v3);
        psq  += (v0 * v0 + v1 * v1) + (v2 * v2 + v3 * v3);
        __syncthreads();
    }
    sred[0][tid] = psum; sred[1][tid] = psq;
    __syncthreads();
    if (tid < 64) {
        float s  = sred[0][tid] + sred[0][tid + 64] + sred[0][tid + 128] + sred[0][tid + 192];
        float sq = sred[1][tid] + sred[1][tid + 64] + sred[1][tid + 128] + sred[1][tid + 192];
        g_part[1][0][blockIdx.x * C + tid] = s;
        g_part[1][1][blockIdx.x * C + tid] = sq;
    }
}

// ---------------- K5: final BN3 --------------------------------------------
__global__ void k5_bn3(float* __restrict__ out,
                       const float* __restrict__ gamma3,
                       const float* __restrict__ beta3) {
    int i = blockIdx.x * 256 + threadIdx.x;
    int c = i & (C - 1);
    float mu = g_bn[2 * C + c], rs = g_bn[3 * C + c];
    out[i] = fmaf((g_v[i] - mu) * rs, gamma3[c], beta3[c]);
}

// ---------------- launch ----------------------------------------------------
extern "C" void kernel_launch(void* const* d_in, const int* in_sizes, int n_in,
                              void* d_out, int out_size) {
    const float* x      = (const float*)d_in[0];
    const float* w_s    = (const float*)d_in[1];
    const float* w_h    = (const float*)d_in[2];
    const float* b_h    = (const float*)d_in[3];
    const float* w_lin  = (const float*)d_in[4];
    const float* b_lin  = (const float*)d_in[5];
    const float* w_p1   = (const float*)d_in[6];
    const float* b_p1   = (const float*)d_in[7];
    const float* w_p2   = (const float*)d_in[8];
    const float* b_p2   = (const float*)d_in[9];
    const float* gamma2 = (const float*)d_in[10];
    const float* beta2  = (const float*)d_in[11];
    const float* gamma3 = (const float*)d_in[12];
    const float* beta3  = (const float*)d_in[13];
    float* out = (float*)d_out;

    k1_gemm_hs<<<NN / 8, C>>>(x, w_h, b_h, w_s);
    k2_knn<<<NN / 32, 256>>>();
    k3_agg<<<PART, 256>>>(x, w_lin, b_lin);
    kfin_stats<<<1, 1024>>>(0);
    k4_mlp<<<PART, 256>>>(w_p1, b_p1, w_p2, b_p2, gamma2, beta2);
    kfin_stats<<<1, 1024>>>(1);
    k5_bn3<<<(NN * C) / 256, 256>>>(out, gamma3, beta3);
}

// round 6
// speedup vs baseline: 5.6501x; 1.3747x over previous
#include <cuda_runtime.h>
#include <math.h>

#define NN 16384
#define C 64
#define KNN 40
#define TILE4 1024     // float4 candidates per smem tile
#define CAP 128        // collection capacity per query
#define QPW 4          // queries per warp in kNN
#define PART 512       // partial-reduction blocks for BN stats

// ---------------- scratch (device globals; no allocation allowed) ----------
__device__ float  g_h[NN * C];       // propagated features
__device__ float4 g_s4[NN];          // learned coords (x,y,z,|s|^2)
__device__ int    g_idx[NN * KNN];   // kNN indices
__device__ float  g_ew[NN * KNN];    // edge weights
__device__ float  g_t[NN * C];       // pre-BN2 tensor
__device__ float  g_v[NN * C];       // pre-BN3 tensor
__device__ float  g_part[2][2][PART * C];
__device__ float  g_bn[4 * C];       // mu2, rstd2, mu3, rstd3

// ---------------- K1: h = x@w_h + b_h ; s = x@w_s ; pack s4 ----------------
__global__ void k1_gemm_hs(const float* __restrict__ x,
                           const float* __restrict__ w_h,
                           const float* __restrict__ b_h,
                           const float* __restrict__ w_s) {
    const int ROWS = 8;
    __shared__ float sx[ROWS][C];
    __shared__ float ss[ROWS][3];
    int base = blockIdx.x * ROWS;
    int c = threadIdx.x; // 64 threads

    #pragma unroll
    for (int r = 0; r < ROWS; r++) sx[r][c] = x[(base + r) * C + c];
    __syncthreads();

    float bias = b_h[c];
    float acc[ROWS];
    #pragma unroll
    for (int r = 0; r < ROWS; r++) acc[r] = bias;
    for (int rr = 0; rr < C; rr++) {
        float wv = w_h[rr * C + c];
        #pragma unroll
        for (int r = 0; r < ROWS; r++) acc[r] = fmaf(sx[r][rr], wv, acc[r]);
    }
    #pragma unroll
    for (int r = 0; r < ROWS; r++) g_h[(base + r) * C + c] = acc[r];

    if (c < ROWS * 3) {
        int r = c / 3, d = c % 3;
        float a = 0.f;
        for (int rr = 0; rr < C; rr++) a = fmaf(sx[r][rr], w_s[rr * 3 + d], a);
        ss[r][d] = a;
    }
    __syncthreads();
    if (c < ROWS) {
        float a = ss[c][0], b = ss[c][1], d = ss[c][2];
        g_s4[base + c] = make_float4(a, b, d, a * a + b * b + d * d);
    }
}

// ---------------- K2: exact two-pass threshold kNN (branchless sweeps) -----
__device__ __forceinline__ float qdist(float qx, float qy, float qz, float qw,
                                       float4 cp) {
    float dot = fmaf(qx, cp.x, fmaf(qy, cp.y, qz * cp.z));
    return fmaf(-2.0f, dot, qw + cp.w);   // reference selection form
}

__global__ void __launch_bounds__(256) k2_knn() {
    __shared__ float4 tile[TILE4];
    __shared__ float  skey[32][CAP];
    __shared__ int    sidx[32][CAP];
    const unsigned FULL = 0xffffffffu;
    const float INF = 3.4e38f;
    int lane = threadIdx.x & 31;
    int wrp  = threadIdx.x >> 5;       // 8 warps
    int qbase = blockIdx.x * 32 + wrp * QPW;

    float qx[QPW], qy[QPW], qz[QPW], qw[QPW];
    #pragma unroll
    for (int q = 0; q < QPW; q++) {
        float4 qq = g_s4[qbase + q];
        qx[q] = qq.x; qy[q] = qq.y; qz[q] = qq.z; qw[q] = qq.w;
    }

    // ---- sweep A: lane-private branchless sorted top-3 (values only) ----
    float t0[QPW], t1[QPW], t2[QPW];
    #pragma unroll
    for (int q = 0; q < QPW; q++) { t0[q] = INF; t1[q] = INF; t2[q] = INF; }

    for (int t = 0; t < NN; t += TILE4) {
        __syncthreads();
        for (int j = threadIdx.x; j < TILE4; j += 256) tile[j] = g_s4[t + j];
        __syncthreads();
        #pragma unroll 2
        for (int jb = 0; jb < TILE4 / 32; jb++) {
            float4 cp = tile[jb * 32 + lane];
            #pragma unroll
            for (int q = 0; q < QPW; q++) {
                float a = qdist(qx[q], qy[q], qz[q], qw[q], cp);
                float h0 = fmaxf(a, t0[q]);  t0[q] = fminf(a, t0[q]);
                float h1 = fmaxf(h0, t1[q]); t1[q] = fminf(h0, t1[q]);
                t2[q] = fminf(t2[q], h1);
            }
        }
    }

    // ---- tau[q] = 40th smallest of kept 96 values (>= true 40th dist) ----
    float tau[QPW];
    #pragma unroll 1
    for (int q = 0; q < QPW; q++) {
        float h0 = t0[q], h1 = t1[q], h2 = t2[q];
        float m = INF;
        #pragma unroll 1
        for (int r = 0; r < KNN; r++) {
            m = h0;
            #pragma unroll
            for (int o = 16; o; o >>= 1) m = fminf(m, __shfl_xor_sync(FULL, m, o));
            unsigned bb = __ballot_sync(FULL, h0 == m);
            if (lane == __ffs(bb) - 1) { h0 = h1; h1 = h2; h2 = INF; }
        }
        tau[q] = m;
    }

    // ---- sweep B: collect all candidates with d2 <= tau (combined test) ----
    int cnt[QPW];
    #pragma unroll
    for (int q = 0; q < QPW; q++) cnt[q] = 0;
    unsigned ltmask = (1u << lane) - 1u;

    for (int t = 0; t < NN; t += TILE4) {
        __syncthreads();
        for (int j = threadIdx.x; j < TILE4; j += 256) tile[j] = g_s4[t + j];
        __syncthreads();
        #pragma unroll 2
        for (int jb = 0; jb < TILE4 / 32; jb++) {
            float4 cp = tile[jb * 32 + lane];
            int ci = t + jb * 32 + lane;
            float d2v[QPW];
            bool anyhit = false;
            #pragma unroll
            for (int q = 0; q < QPW; q++) {
                d2v[q] = qdist(qx[q], qy[q], qz[q], qw[q], cp);
                anyhit = anyhit || (d2v[q] <= tau[q]);
            }
            if (__ballot_sync(FULL, anyhit)) {
                #pragma unroll
                for (int q = 0; q < QPW; q++) {
                    bool hit = (d2v[q] <= tau[q]);
                    unsigned mm = __ballot_sync(FULL, hit);
                    if (mm) {
                        int pos = cnt[q] + __popc(mm & ltmask);
                        if (hit && pos < CAP) {
                            skey[wrp * QPW + q][pos] = d2v[q];
                            sidx[wrp * QPW + q][pos] = ci;
                        }
                        cnt[q] += __popc(mm);
                    }
                }
            }
        }
    }

    // ---- final: exact rank-(d2,idx) top-40 from the small collection ----
    #pragma unroll 1
    for (int q = 0; q < QPW; q++) {
        int n = cnt[q] < CAP ? cnt[q] : CAP;
        int qs = wrp * QPW + q;
        int qg = qbase + q;
        #pragma unroll 1
        for (int base = 0; base < n; base += 32) {
            int p = base + lane;
            if (p < n) {
                float d = skey[qs][p];
                int  id = sidx[qs][p];
                int rank = 0;
                for (int e = 0; e < n; e++) {
                    float de = skey[qs][e];
                    int   ie = sidx[qs][e];
                    rank += (de < d) || (de == d && ie < id);
                }
                if (rank < KNN) {
                    float4 cp = g_s4[id];
                    float dx = qx[q] - cp.x, dy = qy[q] - cp.y, dz = qz[q] - cp.z;
                    g_idx[qg * KNN + rank] = id;
                    g_ew[qg * KNN + rank]  = expf(-(dx * dx + dy * dy + dz * dz + 1e-6f));
                }
            }
        }
    }
}

// ---------------- K3: aggregate + lin + residual; BN2 partials -------------
__global__ void __launch_bounds__(256) k3_agg(const float* __restrict__ x,
                                              const float* __restrict__ w_lin,
                                              const float* __restrict__ b_lin) {
    __shared__ float  swl[3 * C * C];      // 48KB
    __shared__ float4 shs4[4][3 * C];      // 12KB
    __shared__ float  sred[2][256];
    int tid = threadIdx.x;
    int g = tid >> 6, c = tid & 63;

    for (int i = tid; i < 3 * C * C; i += 256) swl[i] = w_lin[i];
    float blc = b_lin[c];
    float psum = 0.f, psq = 0.f;

    for (int ii = blockIdx.x * 16; ii < NN; ii += PART * 16) {
        float mv[4], mxv[4], xr[4];
        #pragma unroll
        for (int b = 0; b < 4; b++) {
            int i = ii + g * 4 + b;
            const int*   ip = &g_idx[i * KNN];
            const float* wp = &g_ew[i * KNN];
            float m = 0.f, mx = -3.4e38f;
            #pragma unroll 8
            for (int k = 0; k < KNN; k++) {
                float msg = wp[k] * g_h[ip[k] * C + c];
                m += msg;
                mx = fmaxf(mx, msg);
            }
            mv[b] = m * (1.0f / KNN); mxv[b] = mx;
            xr[b] = x[i * C + c];
        }
        #pragma unroll
        for (int b = 0; b < 4; b++) {
            ((float*)&shs4[g][c])[b]         = mv[b];
            ((float*)&shs4[g][C + c])[b]     = mxv[b];
            ((float*)&shs4[g][2 * C + c])[b] = xr[b];
        }
        __syncthreads();
        float a0 = 0.f, a1 = 0.f, a2 = 0.f, a3 = 0.f;
        #pragma unroll 4
        for (int r = 0; r < 3 * C; r++) {
            float4 v = shs4[g][r];
            float w = swl[r * C + c];
            a0 = fmaf(v.x, w, a0); a1 = fmaf(v.y, w, a1);
            a2 = fmaf(v.z, w, a2); a3 = fmaf(v.w, w, a3);
        }
        float tv0 = a0 + blc + xr[0], tv1 = a1 + blc + xr[1];
        float tv2 = a2 + blc + xr[2], tv3 = a3 + blc + xr[3];
        int i0 = ii + g * 4;
        g_t[(i0 + 0) * C + c] = tv0; g_t[(i0 + 1) * C + c] = tv1;
        g_t[(i0 + 2) * C + c] = tv2; g_t[(i0 + 3) * C + c] = tv3;
        psum += (tv0 + tv1) + (tv2 + tv3);
        psq  += (tv0 * tv0 + tv1 * tv1) + (tv2 * tv2 + tv3 * tv3);
        __syncthreads();
    }
    sred[0][tid] = psum; sred[1][tid] = psq;
    __syncthreads();
    if (tid < 64) {
        float s  = sred[0][tid] + sred[0][tid + 64] + sred[0][tid + 128] + sred[0][tid + 192];
        float sq = sred[1][tid] + sred[1][tid + 64] + sred[1][tid + 128] + sred[1][tid + 192];
        g_part[0][0][blockIdx.x * C + tid] = s;
        g_part[0][1][blockIdx.x * C + tid] = sq;
    }
}

// ---------------- finalize BN stats (deterministic, parallel) --------------
__global__ void kfin_stats(int stage) {
    __shared__ float red[2][1024];
    int t = threadIdx.x;             // 1024 threads
    int c = t & (C - 1);
    int g = t >> 6;                  // 16 groups
    float s = 0.f, sq = 0.f;
    for (int p = g; p < PART; p += 16) {
        s  += g_part[stage][0][p * C + c];
        sq += g_part[stage][1][p * C + c];
    }
    red[0][t] = s; red[1][t] = sq;
    __syncthreads();
    #pragma unroll
    for (int off = 512; off >= 64; off >>= 1) {
        if (t < off) { red[0][t] += red[0][t + off]; red[1][t] += red[1][t + off]; }
        __syncthreads();
    }
    if (t < C) {
        float mu  = red[0][t] * (1.0f / NN);
        float var = red[1][t] * (1.0f / NN) - mu * mu;
        g_bn[stage * 2 * C + t]     = mu;
        g_bn[stage * 2 * C + C + t] = rsqrtf(var + 1e-5f);
    }
}

// ---------------- K4: BN2 + MLP + residual; BN3 partials -------------------
__global__ void __launch_bounds__(256) k4_mlp(const float* __restrict__ w_p1,
                                              const float* __restrict__ b_p1,
                                              const float* __restrict__ w_p2,
                                              const float* __restrict__ b_p2,
                                              const float* __restrict__ gamma2,
                                              const float* __restrict__ beta2) {
    __shared__ float  w1s[C * C], w2s[C * C];   // 32KB
    __shared__ float4 sy4[4][C], su4[4][C];     // 4KB
    __shared__ float  sred[2][256];
    int tid = threadIdx.x;
    int g = tid >> 6, c = tid & 63;

    for (int i = tid; i < C * C; i += 256) { w1s[i] = w_p1[i]; w2s[i] = w_p2[i]; }
    float mu = g_bn[c], rs = g_bn[C + c];
    float g2 = gamma2[c], be2 = beta2[c];
    float bp1 = b_p1[c], bp2 = b_p2[c];
    float psum = 0.f, psq = 0.f;

    for (int ii = blockIdx.x * 16; ii < NN; ii += PART * 16) {
        int i0 = ii + g * 4;
        float y[4];
        #pragma unroll
        for (int b = 0; b < 4; b++) {
            float tv = g_t[(i0 + b) * C + c];
            y[b] = fmaf((tv - mu) * rs, g2, be2);
            ((float*)&sy4[g][c])[b] = y[b];
        }
        __syncthreads();
        float a0 = 0.f, a1 = 0.f, a2 = 0.f, a3 = 0.f;
        #pragma unroll 4
        for (int r = 0; r < C; r++) {
            float4 v = sy4[g][r];
            float w = w1s[r * C + c];
            a0 = fmaf(v.x, w, a0); a1 = fmaf(v.y, w, a1);
            a2 = fmaf(v.z, w, a2); a3 = fmaf(v.w, w, a3);
        }
        a0 += bp1; a1 += bp1; a2 += bp1; a3 += bp1;
        a0 = (a0 > 0.f) ? a0 : expm1f(a0);
        a1 = (a1 > 0.f) ? a1 : expm1f(a1);
        a2 = (a2 > 0.f) ? a2 : expm1f(a2);
        a3 = (a3 > 0.f) ? a3 : expm1f(a3);
        ((float*)&su4[g][c])[0] = a0; ((float*)&su4[g][c])[1] = a1;
        ((float*)&su4[g][c])[2] = a2; ((float*)&su4[g][c])[3] = a3;
        __syncthreads();
        float z0 = 0.f, z1 = 0.f, z2 = 0.f, z3 = 0.f;
        #pragma unroll 4
        for (int r = 0; r < C; r++) {
            float4 v = su4[g][r];
            float w = w2s[r * C + c];
            z0 = fmaf(v.x, w, z0); z1 = fmaf(v.y, w, z1);
            z2 = fmaf(v.z, w, z2); z3 = fmaf(v.w, w, z3);
        }
        float v0 = y[0] + z0 + bp2, v1 = y[1] + z1 + bp2;
        float v2 = y[2] + z2 + bp2, v3 = y[3] + z3 + bp2;
        g_v[(i0 + 0) * C + c] = v0; g_v[(i0 + 1) * C + c] = v1;
        g_v[(i0 + 2) * C + c] = v2; g_v[(i0 + 3) * C + c] = v3;
        psum += (v0 + v1) + (v2 + v3);
        psq  += (v0 * v0 + v1 * v1) + (v2 * v2 + v3 * v3);
        __syncthreads();
    }
    sred[0][tid] = psum; sred[1][tid] = psq;
    __syncthreads();
    if (tid < 64) {
        float s  = sred[0][tid] + sred[0][tid + 64] + sred[0][tid + 128] + sred[0][tid + 192];
        float sq = sred[1][tid] + sred[1][tid + 64] + sred[1][tid + 128] + sred[1][tid + 192];
        g_part[1][0][blockIdx.x * C + tid] = s;
        g_part[1][1][blockIdx.x * C + tid] = sq;
    }
}

// ---------------- K5: final BN3 --------------------------------------------
__global__ void k5_bn3(float* __restrict__ out,
                       const float* __restrict__ gamma3,
                       const float* __restrict__ beta3) {
    int i = blockIdx.x * 256 + threadIdx.x;
    int c = i & (C - 1);
    float mu = g_bn[2 * C + c], rs = g_bn[3 * C + c];
    out[i] = fmaf((g_v[i] - mu) * rs, gamma3[c], beta3[c]);
}

// ---------------- launch ----------------------------------------------------
extern "C" void kernel_launch(void* const* d_in, const int* in_sizes, int n_in,
                              void* d_out, int out_size) {
    const float* x      = (const float*)d_in[0];
    const float* w_s    = (const float*)d_in[1];
    const float* w_h    = (const float*)d_in[2];
    const float* b_h    = (const float*)d_in[3];
    const float* w_lin  = (const float*)d_in[4];
    const float* b_lin  = (const float*)d_in[5];
    const float* w_p1   = (const float*)d_in[6];
    const float* b_p1   = (const float*)d_in[7];
    const float* w_p2   = (const float*)d_in[8];
    const float* b_p2   = (const float*)d_in[9];
    const float* gamma2 = (const float*)d_in[10];
    const float* beta2  = (const float*)d_in[11];
    const float* gamma3 = (const float*)d_in[12];
    const float* beta3  = (const float*)d_in[13];
    float* out = (float*)d_out;

    k1_gemm_hs<<<NN / 8, C>>>(x, w_h, b_h, w_s);
    k2_knn<<<NN / 32, 256>>>();
    k3_agg<<<PART, 256>>>(x, w_lin, b_lin);
    kfin_stats<<<1, 1024>>>(0);
    k4_mlp<<<PART, 256>>>(w_p1, b_p1, w_p2, b_p2, gamma2, beta2);
    kfin_stats<<<1, 1024>>>(1);
    k5_bn3<<<(NN * C) / 256, 256>>>(out, gamma3, beta3);
}

// round 10
// speedup vs baseline: 6.3561x; 1.1250x over previous
#include <cuda_runtime.h>
#include <math.h>

#define NN 16384
#define C 64
#define KNN 40
#define TILE4 1024     // float4 candidates per smem tile
#define CAP 128        // collection capacity per query
#define QPW 4          // queries per warp in kNN
#define PART 512       // partial-reduction blocks for BN stats

// ---------------- scratch (device globals; no allocation allowed) ----------
__device__ float  g_h[NN * C];       // propagated features
__device__ float4 g_s4[NN];          // learned coords (x,y,z,|s|^2)
__device__ int    g_idx[NN * KNN];   // kNN indices
__device__ float  g_ew[NN * KNN];    // edge weights
__device__ float  g_t[NN * C];       // pre-BN2 tensor
__device__ float  g_v[NN * C];       // pre-BN3 tensor
__device__ float  g_part[2][2][C * PART];   // transposed: [stage][s|sq][c*PART+p]
__device__ float  g_bn[4 * C];       // mu2, rstd2, mu3, rstd3

// ---------------- K1: h = x@w_h + b_h ; s = x@w_s ; pack s4 ----------------
__global__ void k1_gemm_hs(const float* __restrict__ x,
                           const float* __restrict__ w_h,
                           const float* __restrict__ b_h,
                           const float* __restrict__ w_s) {
    const int ROWS = 8;
    __shared__ float sx[ROWS][C];
    __shared__ float ss[ROWS][3];
    int base = blockIdx.x * ROWS;
    int c = threadIdx.x; // 64 threads

    #pragma unroll
    for (int r = 0; r < ROWS; r++) sx[r][c] = x[(base + r) * C + c];
    __syncthreads();

    float bias = b_h[c];
    float acc[ROWS];
    #pragma unroll
    for (int r = 0; r < ROWS; r++) acc[r] = bias;
    for (int rr = 0; rr < C; rr++) {
        float wv = w_h[rr * C + c];
        #pragma unroll
        for (int r = 0; r < ROWS; r++) acc[r] = fmaf(sx[r][rr], wv, acc[r]);
    }
    #pragma unroll
    for (int r = 0; r < ROWS; r++) g_h[(base + r) * C + c] = acc[r];

    if (c < ROWS * 3) {
        int r = c / 3, d = c % 3;
        float a = 0.f;
        for (int rr = 0; rr < C; rr++) a = fmaf(sx[r][rr], w_s[rr * 3 + d], a);
        ss[r][d] = a;
    }
    __syncthreads();
    if (c < ROWS) {
        float a = ss[c][0], b = ss[c][1], d = ss[c][2];
        g_s4[base + c] = make_float4(a, b, d, a * a + b * b + d * d);
    }
}

// ---------------- K2: exact two-pass threshold kNN (e-transform) -----------
__global__ void __launch_bounds__(256) k2_knn() {
    __shared__ float4 tile[TILE4];          // (x,y,z,w/2)
    __shared__ float  skey[32][CAP];
    __shared__ int    sidx[32][CAP];
    const unsigned FULL = 0xffffffffu;
    const float INF = 3.4e38f;
    int lane = threadIdx.x & 31;
    int wrp  = threadIdx.x >> 5;       // 8 warps
    int qbase = blockIdx.x * 32 + wrp * QPW;

    float qx[QPW], qy[QPW], qz[QPW], qw[QPW];
    #pragma unroll
    for (int q = 0; q < QPW; q++) {
        float4 qq = g_s4[qbase + q];
        qx[q] = qq.x; qy[q] = qq.y; qz[q] = qq.z; qw[q] = qq.w;
    }

    // ---- sweep A: lane-private branchless top-2 of e = w/2 - dot ----
    float t0[QPW], t1[QPW];
    #pragma unroll
    for (int q = 0; q < QPW; q++) { t0[q] = INF; t1[q] = INF; }

    for (int t = 0; t < NN; t += TILE4) {
        __syncthreads();
        for (int j = threadIdx.x; j < TILE4; j += 256) {
            float4 v = g_s4[t + j];
            v.w *= 0.5f;
            tile[j] = v;
        }
        __syncthreads();
        #pragma unroll 2
        for (int jb = 0; jb < TILE4 / 32; jb++) {
            float4 cp = tile[jb * 32 + lane];
            #pragma unroll
            for (int q = 0; q < QPW; q++) {
                float e = fmaf(-qx[q], cp.x,
                          fmaf(-qy[q], cp.y,
                          fmaf(-qz[q], cp.z, cp.w)));        // 3 FFMA (neg folded)
                float h = fmaxf(e, t0[q]);
                t0[q] = fminf(e, t0[q]);
                t1[q] = fminf(t1[q], h);
            }
        }
    }

    // ---- tau[q] = 40th smallest of kept 64 e-values, padded for safety ----
    float tau[QPW];
    #pragma unroll 1
    for (int q = 0; q < QPW; q++) {
        float h0 = t0[q], h1 = t1[q];
        float m = INF;
        #pragma unroll 1
        for (int r = 0; r < KNN; r++) {
            m = h0;
            #pragma unroll
            for (int o = 16; o; o >>= 1) m = fminf(m, __shfl_xor_sync(FULL, m, o));
            unsigned bb = __ballot_sync(FULL, h0 == m);
            if (lane == __ffs(bb) - 1) { h0 = h1; h1 = INF; }
        }
        // pad: covers e-vs-d2 rounding-order inversions; keeps superset property
        tau[q] = m + (fabsf(m) + 0.5f * qw[q] + 2.0f) * 1e-5f;
    }

    // ---- sweep B: collect all candidates with e <= tau ----
    int cnt[QPW];
    #pragma unroll
    for (int q = 0; q < QPW; q++) cnt[q] = 0;
    unsigned ltmask = (1u << lane) - 1u;

    for (int t = 0; t < NN; t += TILE4) {
        __syncthreads();
        for (int j = threadIdx.x; j < TILE4; j += 256) {
            float4 v = g_s4[t + j];
            v.w *= 0.5f;
            tile[j] = v;
        }
        __syncthreads();
        #pragma unroll 2
        for (int jb = 0; jb < TILE4 / 32; jb++) {
            float4 cp = tile[jb * 32 + lane];
            int ci = t + jb * 32 + lane;
            bool hitv[QPW];
            bool anyhit = false;
            #pragma unroll
            for (int q = 0; q < QPW; q++) {
                float e = fmaf(-qx[q], cp.x,
                          fmaf(-qy[q], cp.y,
                          fmaf(-qz[q], cp.z, cp.w)));
                hitv[q] = (e <= tau[q]);
                anyhit = anyhit || hitv[q];
            }
            if (__ballot_sync(FULL, anyhit)) {
                #pragma unroll
                for (int q = 0; q < QPW; q++) {
                    unsigned mm = __ballot_sync(FULL, hitv[q]);
                    if (mm) {
                        int pos = cnt[q] + __popc(mm & ltmask);
                        if (hitv[q] && pos < CAP) sidx[wrp * QPW + q][pos] = ci;
                        cnt[q] += __popc(mm);
                    }
                }
            }
        }
    }

    // ---- final: recompute exact reference-form d2, rank, emit top-40 ----
    #pragma unroll 1
    for (int q = 0; q < QPW; q++) {
        int n = cnt[q] < CAP ? cnt[q] : CAP;
        int qs = wrp * QPW + q;
        int qg = qbase + q;
        for (int p = lane; p < n; p += 32) {
            float4 cp = g_s4[sidx[qs][p]];
            float dot = fmaf(qx[q], cp.x, fmaf(qy[q], cp.y, qz[q] * cp.z));
            skey[qs][p] = fmaf(-2.0f, dot, qw[q] + cp.w);   // reference form
        }
        __syncwarp();
        #pragma unroll 1
        for (int base = 0; base < n; base += 32) {
            int p = base + lane;
            if (p < n) {
                float d = skey[qs][p];
                int  id = sidx[qs][p];
                int rank = 0;
                for (int e = 0; e < n; e++) {
                    float de = skey[qs][e];
                    int   ie = sidx[qs][e];
                    rank += (de < d) || (de == d && ie < id);
                }
                if (rank < KNN) {
                    float4 cp = g_s4[id];
                    float dx = qx[q] - cp.x, dy = qy[q] - cp.y, dz = qz[q] - cp.z;
                    g_idx[qg * KNN + rank] = id;
                    g_ew[qg * KNN + rank]  = expf(-(dx * dx + dy * dy + dz * dz + 1e-6f));
                }
            }
        }
        __syncwarp();
    }
}

// ---------------- K3: aggregate + lin + residual; BN2 partials -------------
__global__ void __launch_bounds__(256) k3_agg(const float* __restrict__ x,
                                              const float* __restrict__ w_lin,
                                              const float* __restrict__ b_lin) {
    __shared__ float  swl[3 * C * C];      // 48KB
    __shared__ float4 shs4[4][3 * C];      // 12KB
    __shared__ float  sred[2][256];
    int tid = threadIdx.x;
    int g = tid >> 6, c = tid & 63;

    for (int i = tid; i < 3 * C * C; i += 256) swl[i] = w_lin[i];
    float blc = b_lin[c];
    float psum = 0.f, psq = 0.f;

    for (int ii = blockIdx.x * 16; ii < NN; ii += PART * 16) {
        float mv[4], mxv[4], xr[4];
        #pragma unroll
        for (int b = 0; b < 4; b++) {
            int i = ii + g * 4 + b;
            const int*   ip = &g_idx[i * KNN];
            const float* wp = &g_ew[i * KNN];
            float m = 0.f, mx = -3.4e38f;
            #pragma unroll 8
            for (int k = 0; k < KNN; k++) {
                float msg = wp[k] * g_h[ip[k] * C + c];
                m += msg;
                mx = fmaxf(mx, msg);
            }
            mv[b] = m * (1.0f / KNN); mxv[b] = mx;
            xr[b] = x[i * C + c];
        }
        #pragma unroll
        for (int b = 0; b < 4; b++) {
            ((float*)&shs4[g][c])[b]         = mv[b];
            ((float*)&shs4[g][C + c])[b]     = mxv[b];
            ((float*)&shs4[g][2 * C + c])[b] = xr[b];
        }
        __syncthreads();
        float a0 = 0.f, a1 = 0.f, a2 = 0.f, a3 = 0.f;
        #pragma unroll 4
        for (int r = 0; r < 3 * C; r++) {
            float4 v = shs4[g][r];
            float w = swl[r * C + c];
            a0 = fmaf(v.x, w, a0); a1 = fmaf(v.y, w, a1);
            a2 = fmaf(v.z, w, a2); a3 = fmaf(v.w, w, a3);
        }
        float tv0 = a0 + blc + xr[0], tv1 = a1 + blc + xr[1];
        float tv2 = a2 + blc + xr[2], tv3 = a3 + blc + xr[3];
        int i0 = ii + g * 4;
        g_t[(i0 + 0) * C + c] = tv0; g_t[(i0 + 1) * C + c] = tv1;
        g_t[(i0 + 2) * C + c] = tv2; g_t[(i0 + 3) * C + c] = tv3;
        psum += (tv0 + tv1) + (tv2 + tv3);
        psq  += (tv0 * tv0 + tv1 * tv1) + (tv2 * tv2 + tv3 * tv3);
        __syncthreads();
    }
    sred[0][tid] = psum; sred[1][tid] = psq;
    __syncthreads();
    if (tid < 64) {
        float s  = sred[0][tid] + sred[0][tid + 64] + sred[0][tid + 128] + sred[0][tid + 192];
        float sq = sred[1][tid] + sred[1][tid + 64] + sred[1][tid + 128] + sred[1][tid + 192];
        g_part[0][0][tid * PART + blockIdx.x] = s;
        g_part[0][1][tid * PART + blockIdx.x] = sq;
    }
}

// ---------------- finalize BN stats (16 blocks, coalesced) -----------------
__global__ void kfin_stats(int stage) {
    __shared__ float red[2][256];
    int t = threadIdx.x;                 // 256 threads
    int c = blockIdx.x * 4 + (t >> 6);   // 4 channels per block
    int g = t & 63;
    float s = 0.f, sq = 0.f;
    for (int p = g; p < PART; p += 64) {
        s  += g_part[stage][0][c * PART + p];
        sq += g_part[stage][1][c * PART + p];
    }
    red[0][t] = s; red[1][t] = sq;
    __syncthreads();
    #pragma unroll
    for (int off = 32; off >= 1; off >>= 1) {
        if (g < off) { red[0][t] += red[0][t + off]; red[1][t] += red[1][t + off]; }
        __syncthreads();
    }
    if (g == 0) {
        float mu  = red[0][t] * (1.0f / NN);
        float var = red[1][t] * (1.0f / NN) - mu * mu;
        g_bn[stage * 2 * C + c]     = mu;
        g_bn[stage * 2 * C + C + c] = rsqrtf(var + 1e-5f);
    }
}

// ---------------- K4: BN2 + MLP + residual; BN3 partials -------------------
__global__ void __launch_bounds__(256) k4_mlp(const float* __restrict__ w_p1,
                                              const float* __restrict__ b_p1,
                                              const float* __restrict__ w_p2,
                                              const float* __restrict__ b_p2,
                                              const float* __restrict__ gamma2,
                                              const float* __restrict__ beta2) {
    __shared__ float  w1s[C * C], w2s[C * C];   // 32KB
    __shared__ float4 sy4[4][C], su4[4][C];     // 4KB
    __shared__ float  sred[2][256];
    int tid = threadIdx.x;
    int g = tid >> 6, c = tid & 63;

    for (int i = tid; i < C * C; i += 256) { w1s[i] = w_p1[i]; w2s[i] = w_p2[i]; }
    float mu = g_bn[c], rs = g_bn[C + c];
    float g2 = gamma2[c], be2 = beta2[c];
    float bp1 = b_p1[c], bp2 = b_p2[c];
    float psum = 0.f, psq = 0.f;

    for (int ii = blockIdx.x * 16; ii < NN; ii += PART * 16) {
        int i0 = ii + g * 4;
        float y[4];
        #pragma unroll
        for (int b = 0; b < 4; b++) {
            float tv = g_t[(i0 + b) * C + c];
            y[b] = fmaf((tv - mu) * rs, g2, be2);
            ((float*)&sy4[g][c])[b] = y[b];
        }
        __syncthreads();
        float a0 = 0.f, a1 = 0.f, a2 = 0.f, a3 = 0.f;
        #pragma unroll 4
        for (int r = 0; r < C; r++) {
            float4 v = sy4[g][r];
            float w = w1s[r * C + c];
            a0 = fmaf(v.x, w, a0); a1 = fmaf(v.y, w, a1);
            a2 = fmaf(v.z, w, a2); a3 = fmaf(v.w, w, a3);
        }
        a0 += bp1; a1 += bp1; a2 += bp1; a3 += bp1;
        a0 = (a0 > 0.f) ? a0 : expm1f(a0);
        a1 = (a1 > 0.f) ? a1 : expm1f(a1);
        a2 = (a2 > 0.f) ? a2 : expm1f(a2);
        a3 = (a3 > 0.f) ? a3 : expm1f(a3);
        ((float*)&su4[g][c])[0] = a0; ((float*)&su4[g][c])[1] = a1;
        ((float*)&su4[g][c])[2] = a2; ((float*)&su4[g][c])[3] = a3;
        __syncthreads();
        float z0 = 0.f, z1 = 0.f, z2 = 0.f, z3 = 0.f;
        #pragma unroll 4
        for (int r = 0; r < C; r++) {
            float4 v = su4[g][r];
            float w = w2s[r * C + c];
            z0 = fmaf(v.x, w, z0); z1 = fmaf(v.y, w, z1);
            z2 = fmaf(v.z, w, z2); z3 = fmaf(v.w, w, z3);
        }
        float v0 = y[0] + z0 + bp2, v1 = y[1] + z1 + bp2;
        float v2 = y[2] + z2 + bp2, v3 = y[3] + z3 + bp2;
        g_v[(i0 + 0) * C + c] = v0; g_v[(i0 + 1) * C + c] = v1;
        g_v[(i0 + 2) * C + c] = v2; g_v[(i0 + 3) * C + c] = v3;
        psum += (v0 + v1) + (v2 + v3);
        psq  += (v0 * v0 + v1 * v1) + (v2 * v2 + v3 * v3);
        __syncthreads();
    }
    sred[0][tid] = psum; sred[1][tid] = psq;
    __syncthreads();
    if (tid < 64) {
        float s  = sred[0][tid] + sred[0][tid + 64] + sred[0][tid + 128] + sred[0][tid + 192];
        float sq = sred[1][tid] + sred[1][tid + 64] + sred[1][tid + 128] + sred[1][tid + 192];
        g_part[1][0][tid * PART + blockIdx.x] = s;
        g_part[1][1][tid * PART + blockIdx.x] = sq;
    }
}

// ---------------- K5: final BN3 --------------------------------------------
__global__ void k5_bn3(float* __restrict__ out,
                       const float* __restrict__ gamma3,
                       const float* __restrict__ beta3) {
    int i = blockIdx.x * 256 + threadIdx.x;
    int c = i & (C - 1);
    float mu = g_bn[2 * C + c], rs = g_bn[3 * C + c];
    out[i] = fmaf((g_v[i] - mu) * rs, gamma3[c], beta3[c]);
}

// ---------------- launch ----------------------------------------------------
extern "C" void kernel_launch(void* const* d_in, const int* in_sizes, int n_in,
                              void* d_out, int out_size) {
    const float* x      = (const float*)d_in[0];
    const float* w_s    = (const float*)d_in[1];
    const float* w_h    = (const float*)d_in[2];
    const float* b_h    = (const float*)d_in[3];
    const float* w_lin  = (const float*)d_in[4];
    const float* b_lin  = (const float*)d_in[5];
    const float* w_p1   = (const float*)d_in[6];
    const float* b_p1   = (const float*)d_in[7];
    const float* w_p2   = (const float*)d_in[8];
    const float* b_p2   = (const float*)d_in[9];
    const float* gamma2 = (const float*)d_in[10];
    const float* beta2  = (const float*)d_in[11];
    const float* gamma3 = (const float*)d_in[12];
    const float* beta3  = (const float*)d_in[13];
    float* out = (float*)d_out;

    k1_gemm_hs<<<NN / 8, C>>>(x, w_h, b_h, w_s);
    k2_knn<<<NN / 32, 256>>>();
    k3_agg<<<PART, 256>>>(x, w_lin, b_lin);
    kfin_stats<<<16, 256>>>(0);
    k4_mlp<<<PART, 256>>>(w_p1, b_p1, w_p2, b_p2, gamma2, beta2);
    kfin_stats<<<16, 256>>>(1);
    k5_bn3<<<(NN * C) / 256, 256>>>(out, gamma3, beta3);
}